// round 16
// baseline (speedup 1.0000x reference)
#include <cuda_runtime.h>
#include <cuda_fp16.h>
#include <cstdint>

// ---------------------------------------------------------------------------
// Problem constants
// ---------------------------------------------------------------------------
#define HH    192
#define WW    192
#define NPIX  (HH*WW)          // 36864
#define NB    8                // 2 halves * batch 4

// ---------------------------------------------------------------------------
// Device scratch
// g_vh : v results fp16, [n(8)][head(4)][pixel][hd(32)]
// g_bw : qkv weights fp16 in mma-fragment order, [pass(3)][kstep(8)][1024 words]
// ---------------------------------------------------------------------------
__device__ __half    g_vh[8*4*NPIX*32];
__device__ uint32_t  g_bw[3*8*1024];

// ---------------------------------------------------------------------------
// fp16 helpers (base-ISA mma.sync m16n8k16)
// ---------------------------------------------------------------------------
__device__ __forceinline__ uint32_t pkh2(float a, float b) {
    __half2 h = __floats2half2_rn(a, b);   // low half = a
    return *reinterpret_cast<uint32_t*>(&h);
}
__device__ __forceinline__ void mma_f16(float* c, const uint4& a, const uint2& b) {
    asm volatile(
        "mma.sync.aligned.m16n8k16.row.col.f32.f16.f16.f32 "
        "{%0,%1,%2,%3}, {%4,%5,%6,%7}, {%8,%9}, {%0,%1,%2,%3};"
        : "+f"(c[0]), "+f"(c[1]), "+f"(c[2]), "+f"(c[3])
        : "r"(a.x), "r"(a.y), "r"(a.z), "r"(a.w), "r"(b.x), "r"(b.y));
}

// ---- fused-kernel smem map (float units) ------------------------------------
// [0 .. 4896)        A tile (4096 fl) / vs_h overlay (2h x 136 x 36 halves)
// [4896 .. 10016)    Ks_h: 4 heads x 64 pix x 40 halves
// [10016 .. 15136)   Qs_h: 4 heads x 64 pix x 40 halves
// [15136 .. 16160)   aw: softmax weights [head(4)][win 16][tok 4][4] fp32
// [16160 .. 16736)   lw_h: lepe weights fp16 [head][tap][hd]
// [16736 .. 16864)   lepe bias fp32 [head][hd]
// [16864 .. 16928)   attn bias fp32 [head][i*4+j]
#define SMF_KH   4896
#define SMF_QH   10016
#define SMF_AW   15136
#define SMF_LWH  16160
#define SMF_LB   16736
#define SMF_BIAS 16864
#define SM_TOT_F (16928*4)     // 67712 B -> 3 CTAs/SM

// ---- v-kernel smem map (float units) -----------------------------------------
// [0..4096) A    [4096..9216) Cs_h (4 x 64 x 40 halves = 5120 floats)
#define SMF_VC  4096
#define SM_TOT_V (9216*4)      // 36864 B

// ---------------------------------------------------------------------------
// Kernel 0: convert qkv weights fp32 [384][128] -> fp16 fragment layout g_bw.
// ---------------------------------------------------------------------------
__global__ void prep_bw(const float* __restrict__ qkv_w)
{
    int i = blockIdx.x*256 + threadIdx.x;   // 0..12287
    int p  = i >> 12;
    int r  = i & 4095;
    int o  = r >> 5;
    int k4 = r & 31;
    float4 v = __ldg((const float4*)(qkv_w + ((size_t)(p*128 + o))*128) + k4);
    int ks  = k4 >> 2;
    int kc  = (k4 & 3) * 4;
    int tg0 = (kc >> 1) & 3;
    int rr  = kc >> 3;
    uint32_t base = (uint32_t)(p*8192 + ks*1024 + (o>>3)*64 + ((o&7)*4 + tg0)*2 + rr);
    g_bw[base    ] = pkh2(v.x, v.y);
    g_bw[base + 2] = pkh2(v.z, v.w);
}

// ---------------------------------------------------------------------------
// Full-K MMA pass: 8 ksteps, A from smem, B fragments direct from g_bw (L1-hot)
// 8 warps: warp tile 32(M) x 32(N), M total 64
// ---------------------------------------------------------------------------
__device__ __forceinline__ void mma_pass(float acc[2][4][4],
                                         const uint32_t* __restrict__ As,
                                         const uint32_t* __restrict__ gB,
                                         int warp_m, int warp_n, int lane)
{
    #pragma unroll
    for (int kg = 0; kg < 8; ++kg) {
        uint4 a[2];
        #pragma unroll
        for (int i = 0; i < 2; ++i) {
            uint32_t u = (uint32_t)((kg*4 + warp_m*2 + i)*32 + lane);
            u ^= (u >> 3) & 7;
            a[i] = *(const uint4*)(As + (size_t)u*4);
        }
        uint2 bf[4];
        #pragma unroll
        for (int j = 0; j < 4; ++j)
            bf[j] = __ldg((const uint2*)(gB + kg*1024 + (warp_n*4 + j)*64 + lane*2));
        #pragma unroll
        for (int i = 0; i < 2; ++i)
            #pragma unroll
            for (int j = 0; j < 4; ++j)
                mma_f16(acc[i][j], a[i], bf[j]);
    }
}

__device__ __forceinline__ void acc_zero(float acc[2][4][4]) {
    #pragma unroll
    for (int i = 0; i < 2; ++i)
        #pragma unroll
        for (int j = 0; j < 4; ++j)
            #pragma unroll
            for (int e = 0; e < 4; ++e) acc[i][j][e] = 0.0f;
}

// acc -> fp16 [head(4)][pix 64][stride 40]  (Ks_h / Qs_h / v-kernel Cs_h)
__device__ __forceinline__ void write_kc_h(const float acc[2][4][4],
                                           __half* __restrict__ K,
                                           int warp_m, int warp_n, int lane)
{
    const int g  = lane >> 2;
    const int tg = lane & 3;
    #pragma unroll
    for (int i = 0; i < 2; ++i) {
        int pl = warp_m*32 + i*16 + g;
        #pragma unroll
        for (int j = 0; j < 4; ++j) {
            int o0 = warp_n*32 + j*8 + 2*tg;
            int h0 = o0 & 3, h1 = (o0 + 1) & 3;
            int hd = o0 >> 2;
            K[(h0*64 + pl    )*40 + hd] = __float2half_rn(acc[i][j][0]);
            K[(h1*64 + pl    )*40 + hd] = __float2half_rn(acc[i][j][1]);
            K[(h0*64 + pl + 8)*40 + hd] = __float2half_rn(acc[i][j][2]);
            K[(h1*64 + pl + 8)*40 + hd] = __float2half_rn(acc[i][j][3]);
        }
    }
}

// ---------------------------------------------------------------------------
// A staging: 64 pixels x 128 k -> fp16 fragment-major + swizzle.
// ---------------------------------------------------------------------------
__device__ __forceinline__ void stage_a(uint32_t* __restrict__ As,
                                        const float* __restrict__ xb,
                                        int pix, int kh)
{
    const int mtile   = pix >> 4;
    const int g       = pix & 7;
    const int rowhalf = (pix >> 3) & 1;
    #pragma unroll 4
    for (int k2 = 0; k2 < 32; k2 += 2) {
        int k = kh*32 + k2;
        float f0 = __ldg(xb + (size_t)k2 * NPIX);
        float f1 = __ldg(xb + (size_t)(k2+1) * NPIX);
        int kstep = k >> 4;
        int kc    = k & 15;
        int colhalf = kc >> 3;
        int tg      = (kc >> 1) & 3;
        uint32_t u = (uint32_t)((kstep*4 + mtile)*32 + g*4 + tg);
        u ^= (u >> 3) & 7;
        As[u*4 + colhalf*2 + rowhalf] = pkh2(f0, f1);
    }
}

// ---------------------------------------------------------------------------
// vs staging for one head-pair: [hh(2)][4x34 halo][36 halves] from fp16 g_vh
// ---------------------------------------------------------------------------
__device__ __forceinline__ void stage_vs(__half* __restrict__ vs_h,
                                         int pair, int tid, size_t n4,
                                         int x0, int y0)
{
    for (int idx = tid; idx < 2*136*8; idx += 256) {
        int hh  = idx / 1088;
        int rem = idx - hh*1088;
        int pix = rem >> 3;
        int c8  = rem & 7;
        int py  = pix / 34;
        int px  = pix - py*34;
        int gy  = y0 - 1 + py;
        int gx  = x0 - 1 + px;
        uint2 p = make_uint2(0u, 0u);
        if (gy >= 0 && gy < HH && gx >= 0 && gx < WW)
            p = *(const uint2*)(g_vh +
                    ((n4 + pair*2 + hh)*NPIX + (size_t)gy*WW + gx)*32 + c8*4);
        *(uint2*)(vs_h + (size_t)(hh*136 + pix)*36 + c8*4) = p;
    }
}

// ---------------------------------------------------------------------------
// Kernel 1: v = 1x1 conv (fp16 GEMM), M=64 linear blocks.
// ---------------------------------------------------------------------------
__global__ void __launch_bounds__(256, 4)
v_kernel(const float* __restrict__ x)
{
    extern __shared__ __align__(16) float smf[];
    uint32_t* As   = (uint32_t*)smf;
    __half*   Cs_h = (__half*)(smf + SMF_VC);

    const int tid    = threadIdx.x;
    const int lane   = tid & 31;
    const int wid    = tid >> 5;
    const int warp_m = wid >> 2;
    const int warp_n = wid & 3;
    const int n      = blockIdx.y;
    const int half_  = n >> 2;
    const int b      = n & 3;
    const int p0     = blockIdx.x * 64;
    const size_t n4  = (size_t)n * 4;

    {
        const int pix = tid & 63;
        const int kh  = tid >> 6;
        const float* xb = x + ((size_t)(b*256 + half_*128 + kh*32)) * NPIX + p0 + pix;
        stage_a(As, xb, pix, kh);
    }
    __syncthreads();

    float acc[2][4][4];
    acc_zero(acc);
    mma_pass(acc, As, g_bw + 2*8192, warp_m, warp_n, lane);   // v weights

    write_kc_h(acc, Cs_h, warp_m, warp_n, lane);
    __syncthreads();

    {
        int h   = tid >> 6;
        int pix = tid & 63;
        const uint4* src = (const uint4*)(Cs_h + (size_t)(h*64 + pix)*40);
        uint4* d = (uint4*)(g_vh + ((n4 + h)*NPIX + (size_t)(p0 + pix))*32);
        #pragma unroll
        for (int c = 0; c < 4; ++c) d[c] = src[c];
    }
}

// ---------------------------------------------------------------------------
// Kernel 2: fused q,k GEMM + single-shot phase1 + pair-looped phase2.
// CTA = 2 rows x 32 cols, 256 threads, 3 CTAs/SM.
// ---------------------------------------------------------------------------
__global__ void __launch_bounds__(256, 3)
qkv_attn_kernel(const float* __restrict__ x,
                const float* __restrict__ lepe_w, const float* __restrict__ lepe_b,
                const float* __restrict__ bias_table, const int* __restrict__ rel_idx,
                float* __restrict__ out)
{
    extern __shared__ __align__(16) float smf[];
    uint32_t* As   = (uint32_t*)smf;
    __half*   vs_h = (__half*)smf;                // overlays A after GEMMs
    __half*   Ks_h = (__half*)(smf + SMF_KH);
    __half*   Qs_h = (__half*)(smf + SMF_QH);
    __half*   lw_h = (__half*)(smf + SMF_LWH);

    const int tid    = threadIdx.x;
    const int lane   = tid & 31;
    const int wid    = tid >> 5;
    const int warp_m = wid >> 2;
    const int warp_n = wid & 3;
    const int n      = blockIdx.z;
    const int half_  = n >> 2;
    const int b      = n & 3;
    const int x0     = blockIdx.x * 32;
    const int y0     = blockIdx.y * 2;
    const size_t n4  = (size_t)n * 4;

    // stage per-head constants from raw inputs (tiny, L2-resident)
    for (int idx = tid; idx < 1152; idx += 256) {
        int head = idx / 288;
        int r    = idx % 288;
        int tap  = r >> 5;
        int hd   = r & 31;
        lw_h[idx] = __float2half_rn(__ldg(&lepe_w[(hd*4 + head)*9 + tap]));
    }
    if (tid < 128) {
        smf[SMF_LB + tid] = __ldg(&lepe_b[(tid & 31)*4 + (tid >> 5)]);
    } else if (tid < 192) {
        int t2 = tid - 128;
        int head = t2 >> 4, ij = t2 & 15;
        smf[SMF_BIAS + t2] = __ldg(&bias_table[__ldg(&rel_idx[ij])*4 + head]);
    }

    // stage A: interior 2x32 tile
    {
        const int pix = tid & 63;
        const int kh  = tid >> 6;
        const int gy  = y0 + (pix >> 5);
        const int gx  = x0 + (pix & 31);
        const float* xb = x + ((size_t)(b*256 + half_*128 + kh*32)) * NPIX
                            + (size_t)gy*WW + gx;
        stage_a(As, xb, pix, kh);
    }
    __syncthreads();

    // ---- k pass then q pass, no intermediate syncs (B direct from g_bw) ----
    {
        float acc[2][4][4];
        acc_zero(acc);
        mma_pass(acc, As, g_bw + 1*8192, warp_m, warp_n, lane);
        write_kc_h(acc, Ks_h, warp_m, warp_n, lane);

        acc_zero(acc);
        mma_pass(acc, As, g_bw, warp_m, warp_n, lane);
        write_kc_h(acc, Qs_h, warp_m, warp_n, lane);   // all 4 heads
    }
    __syncthreads();      // Ks/Qs visible; A dead -> vs overlay allowed

    const float scale = 0.17677669529663687f;  // 1/sqrt(32)

    // ---- stage vs for pair 0, then phase 1 (all heads); one sync covers both
    stage_vs(vs_h, 0, tid, n4, x0, y0);
    {
        const int head = tid >> 6;
        const int t    = tid & 63;
        const int w    = t >> 2;
        const int i    = t & 3;
        const int sy   = i >> 1, sx = i & 1;
        const int lx   = 2*w + sx;

        uint32_t qh[16];
        {
            const uint4* qp = (const uint4*)(Qs_h + (size_t)(head*64 + sy*32 + lx)*40);
            #pragma unroll
            for (int r = 0; r < 4; ++r) *((uint4*)qh + r) = qp[r];
        }
        float lg[4];
        #pragma unroll
        for (int j = 0; j < 4; ++j) {
            const uint4* kp = (const uint4*)(Ks_h +
                (size_t)(head*64 + (j>>1)*32 + 2*w + (j&1))*40);
            float s = 0.f;
            #pragma unroll
            for (int r = 0; r < 4; ++r) {
                uint4 kk = kp[r];
                const uint32_t* kw = (const uint32_t*)&kk;
                #pragma unroll
                for (int u = 0; u < 4; ++u) {
                    float2 kf = __half22float2(*(const __half2*)&kw[u]);
                    float2 qf = __half22float2(*(const __half2*)&qh[r*4 + u]);
                    s = fmaf(qf.x, kf.x, s);
                    s = fmaf(qf.y, kf.y, s);
                }
            }
            lg[j] = s*scale + smf[SMF_BIAS + head*16 + i*4 + j];
        }
        float m  = fmaxf(fmaxf(lg[0], lg[1]), fmaxf(lg[2], lg[3]));
        float a0 = expf(lg[0] - m);
        float a1 = expf(lg[1] - m);
        float a2 = expf(lg[2] - m);
        float a3 = expf(lg[3] - m);
        float inv = 1.0f / (a0 + a1 + a2 + a3);
        *(float4*)(smf + SMF_AW + (size_t)(head*16 + w)*16 + i*4) =
            make_float4(a0*inv, a1*inv, a2*inv, a3*inv);
    }
    __syncthreads();      // aw + vs(pair0) visible

    // ---- pair loop: phase 2 only ----
    #pragma unroll 1
    for (int pair = 0; pair < 2; ++pair) {
        {
            const int hp   = tid >> 7;
            const int rem  = tid & 127;
            const int w    = rem >> 3;
            const int c8   = rem & 7;
            const int head = pair*2 + hp;

            float a[16];
            {
                const float* awp = smf + SMF_AW + (size_t)(head*16 + w)*16;
                #pragma unroll
                for (int r = 0; r < 4; ++r)
                    *(float4*)(a + r*4) = *(const float4*)(awp + r*4);
            }
            uint2 wvh[9];
            {
                const __half* lwp = lw_h + head*288;
                #pragma unroll
                for (int tp = 0; tp < 9; ++tp)
                    wvh[tp] = *(const uint2*)(lwp + tp*32 + c8*4);
            }
            float4 bb = *(const float4*)(smf + SMF_LB + head*32 + c8*4);

            float accp[4][4];
            #pragma unroll
            for (int i = 0; i < 4; ++i) {
                accp[i][0] = bb.x; accp[i][1] = bb.y;
                accp[i][2] = bb.z; accp[i][3] = bb.w;
            }

            const __half* vbase = vs_h + (size_t)hp*136*36;

            #pragma unroll
            for (int ty = 0; ty < 4; ++ty) {
                #pragma unroll
                for (int tx = 0; tx < 4; ++tx) {
                    const uint2 pv = *(const uint2*)(vbase +
                        (size_t)(ty*34 + 2*w + tx)*36 + c8*4);
                    float2 f01 = __half22float2(*(const __half2*)&pv.x);
                    float2 f23 = __half22float2(*(const __half2*)&pv.y);
                    float vvf[4] = {f01.x, f01.y, f23.x, f23.y};

                    if (ty >= 1 && ty <= 2 && tx >= 1 && tx <= 2) {
                        const int j = (ty - 1)*2 + (tx - 1);
                        #pragma unroll
                        for (int i = 0; i < 4; ++i) {
                            float aij = a[i*4 + j];
                            #pragma unroll
                            for (int e = 0; e < 4; ++e)
                                accp[i][e] = fmaf(aij, vvf[e], accp[i][e]);
                        }
                    }
                    #pragma unroll
                    for (int i = 0; i < 4; ++i) {
                        const int sy = i >> 1, sx = i & 1;
                        if (ty >= sy && ty <= sy + 2 && tx >= sx && tx <= sx + 2) {
                            const uint2 wh = wvh[(ty - sy)*3 + (tx - sx)];
                            float2 w01 = __half22float2(*(const __half2*)&wh.x);
                            float2 w23 = __half22float2(*(const __half2*)&wh.y);
                            accp[i][0] = fmaf(w01.x, vvf[0], accp[i][0]);
                            accp[i][1] = fmaf(w01.y, vvf[1], accp[i][1]);
                            accp[i][2] = fmaf(w23.x, vvf[2], accp[i][2]);
                            accp[i][3] = fmaf(w23.y, vvf[3], accp[i][3]);
                        }
                    }
                }
            }

            // packed float2 stores: (sx=0, sx=1) pair per row -> STG.64
            #pragma unroll
            for (int syi = 0; syi < 2; ++syi) {
                const size_t obr = ((size_t)(b*256 + half_*128 + head))*NPIX
                                 + (size_t)(y0 + syi)*WW + (x0 + 2*w);
                #pragma unroll
                for (int e = 0; e < 4; ++e)
                    *(float2*)(out + obr + (size_t)(c8*4 + e)*4*NPIX) =
                        make_float2(accp[syi*2 + 0][e], accp[syi*2 + 1][e]);
            }
        }

        if (pair == 0) {
            __syncthreads();               // vs(pair0) reads done
            stage_vs(vs_h, 1, tid, n4, x0, y0);
            __syncthreads();               // vs(pair1) visible
        }
    }
}

// ---------------------------------------------------------------------------
// Launcher
// ---------------------------------------------------------------------------
extern "C" void kernel_launch(void* const* d_in, const int* in_sizes, int n_in,
                              void* d_out, int out_size)
{
    const float* x          = (const float*)d_in[0];
    const float* qkv_w      = (const float*)d_in[1];
    const float* lepe_w     = (const float*)d_in[2];
    const float* lepe_b     = (const float*)d_in[3];
    const float* bias_table = (const float*)d_in[4];
    const int*   rel_idx    = (const int*)  d_in[5];
    float* out = (float*)d_out;

    cudaFuncSetAttribute(v_kernel, cudaFuncAttributeMaxDynamicSharedMemorySize, SM_TOT_V);
    cudaFuncSetAttribute(qkv_attn_kernel, cudaFuncAttributeMaxDynamicSharedMemorySize, SM_TOT_F);

    prep_bw<<<48, 256>>>(qkv_w);

    dim3 gv(NPIX/64, NB);            // 576 x 8
    v_kernel<<<gv, 256, SM_TOT_V>>>(x);

    dim3 gf(WW/32, HH/2, NB);        // 6 x 96 x 8
    qkv_attn_kernel<<<gf, 256, SM_TOT_F>>>(x, lepe_w, lepe_b,
                                           bias_table, rel_idx, out);
}